// round 14
// baseline (speedup 1.0000x reference)
#include <cuda_runtime.h>
#include <cuda_fp16.h>
#include <cstdint>

// Shapes: B=2, C=64, 4C=256, H=W=256, WS=8, hn=wn=32, P=64, DMAX=48
#define HW    65536
#define CHW4  16777216   // 256*65536
#define CHW1  4194304    // 64*65536
#define HALF_OUT 8388608 // 2*64*65536

// ------------------ device scratch (no runtime allocation) ------------------
// conv1 out, slot-interleaved: word idx = 8 + (z*16+g*4+chunk)*524288 + (y*256+x)*8 + s
__device__ __align__(16) unsigned g_y2[8 + 64L*65536*8];
__device__ float g_Q  [2*64*65536];
__device__ float g_K  [2*64*65536];
__device__ float g_GQ [2*64*65536];    // gather_w(Q, l2r)  flat [b,y,x,c]
__device__ float g_GK [2*64*65536];    // gather_w(K, r2l)
__device__ float g_GXL[2*64*65536];    // gather_w(x_left, l2r)
__device__ float g_GXR[2*64*65536];    // gather_w(x_right, r2l)
__device__ unsigned g_w1h[4*4*4608];   // per (g,chunk): [tap9][oc64][slot8] half2
__device__ unsigned g_w2h[4*4*4608];
__device__ float g_aff[4][256];        // [0]=aL [1]=bL [2]=aR [3]=bR

__device__ __forceinline__ unsigned h2bits(float lo, float hi) {
    __half2 h = __floats2half2_rn(lo, hi);
    return *(unsigned*)&h;
}

#define MMA_F16(d, A0, A1, B)                                               \
    asm volatile("mma.sync.aligned.m16n8k16.row.col.f32.f16.f16.f32 "       \
        "{%0,%1,%2,%3}, {%4,%5,%6,%7}, {%8,%9}, {%0,%1,%2,%3};"             \
        : "+f"((d)[0]), "+f"((d)[1]), "+f"((d)[2]), "+f"((d)[3])            \
        : "r"((A0).x), "r"((A1).x), "r"((A0).y), "r"((A1).y),               \
          "r"((B).x), "r"((B).y))
#define MMA_F16S(d, a0, a1, a2, a3, b0, b1)                                 \
    asm volatile("mma.sync.aligned.m16n8k16.row.col.f32.f16.f16.f32 "       \
        "{%0,%1,%2,%3}, {%4,%5,%6,%7}, {%8,%9}, {%0,%1,%2,%3};"             \
        : "+f"((d)[0]), "+f"((d)[1]), "+f"((d)[2]), "+f"((d)[3])            \
        : "r"(a0), "r"(a1), "r"(a2), "r"(a3), "r"(b0), "r"(b1))

// ------------------ BN batch stats ------------------
__global__ void bn_stats_kernel(const float* __restrict__ cat,
                                const float* __restrict__ gamma,
                                const float* __restrict__ beta, int side)
{
    int ch = blockIdx.x, tid = threadIdx.x;
    const float* p0 = cat + (size_t)ch * HW;
    const float* p1 = cat + (size_t)CHW4 + (size_t)ch * HW;
    double s = 0.0, sq = 0.0;
    for (int e = tid; e < HW; e += 256) {
        float v0 = p0[e], v1 = p1[e];
        s  += (double)v0 + (double)v1;
        sq += (double)v0 * v0 + (double)v1 * v1;
    }
    __shared__ double sh_s[256], sh_q[256];
    sh_s[tid] = s; sh_q[tid] = sq;
    __syncthreads();
    for (int st = 128; st > 0; st >>= 1) {
        if (tid < st) { sh_s[tid] += sh_s[tid+st]; sh_q[tid] += sh_q[tid+st]; }
        __syncthreads();
    }
    if (tid == 0) {
        double n = 131072.0;
        double mu  = sh_s[0] / n;
        double var = sh_q[0] / n - mu * mu;
        float a = gamma[ch] * rsqrtf((float)var + 1e-5f);
        g_aff[side*2][ch]   = a;
        g_aff[side*2+1][ch] = beta[ch] - a * (float)mu;
    }
}

// ------------------ weight prep ------------------
__global__ void prep_w_kernel(const float* __restrict__ w1, const float* __restrict__ w2)
{
    int gc = blockIdx.x;            // g*4 + chunk
    int layer = blockIdx.y;
    const float* w = layer ? w2 : w1;
    unsigned* dst = (layer ? g_w2h : g_w1h) + gc * 4608;
    int g = gc >> 2, chunk = gc & 3;
    for (int e = threadIdx.x; e < 4608; e += 256) {
        int tap = e >> 9, oc = (e >> 3) & 63, s = e & 7;
        int p = (s >> 1) + 4*(s & 1);
        int ic = chunk*16 + 2*p;
        int o = g*64 + oc;
        dst[e] = h2bits(w[(o*64 + ic)*9 + tap], w[(o*64 + ic + 1)*9 + tap]);
    }
}

// ------------------ MMA tap loop: 2mf x 8nf per warp ------------------
__device__ __forceinline__ void mma_taps(const unsigned* sIn, const unsigned* sW,
    int wset, int wrow, int wx, int r4, int c4, float acc[2][8][4])
{
    #pragma unroll
    for (int tap = 0; tap < 9; tap++) {
        const int dy = tap / 3, dx = tap - dy*3;
        const unsigned* wB = sW + tap*512;
        uint2 A0[2], A1[2];
        #pragma unroll
        for (int mf = 0; mf < 2; mf++) {
            int oc0 = wset*32 + mf*16 + r4;
            A0[mf] = *(const uint2*)(wB + oc0*8 + 2*c4);
            A1[mf] = *(const uint2*)(wB + (oc0 + 8)*8 + 2*c4);
        }
        const unsigned* bp = sIn + (wrow + dy)*1064 + (wx + dx + r4)*8 + 2*c4;
        #pragma unroll
        for (int nf = 0; nf < 8; nf++) {
            uint2 Bf = *(const uint2*)(bp + nf*64);
            MMA_F16(acc[0][nf], A0[0], A1[0], Bf);
            MMA_F16(acc[1][nf], A0[1], A1[1], Bf);
        }
    }
}

// ------------------ conv1: slot-interleaved fp16 out ------------------
__global__ __launch_bounds__(256, 2) void conv1_kernel(
    const float* __restrict__ cat_l, const float* __restrict__ cat_r,
    const float* __restrict__ b1)
{
    __shared__ __align__(16) unsigned sm[8864];   // sIn 4256 + sW 4608
    unsigned* sIn = sm;
    unsigned* sW  = sm + 4256;
    int tile = blockIdx.x, g = blockIdx.y, z = blockIdx.z;
    int side = z >> 1, b = z & 1;
    int y0 = (tile >> 1) * 2, x0 = (tile & 1) * 128;
    int tid = threadIdx.x, lane = tid & 31, warp = tid >> 5;
    int wset = warp >> 2, w4 = warp & 3, wrow = w4 >> 1, wx = (w4 & 1) * 64;
    int r4 = lane >> 2, c4 = lane & 3;

    float acc[2][8][4];
    #pragma unroll
    for (int m = 0; m < 2; m++)
        #pragma unroll
        for (int n = 0; n < 8; n++)
            #pragma unroll
            for (int k = 0; k < 4; k++) acc[m][n][k] = 0.f;

    const float* cat = side ? cat_r : cat_l;
    const float* fin = cat + (size_t)b*CHW4 + (size_t)(g*64)*HW;
    const float* a_bn = g_aff[side*2] + g*64;
    const float* b_bn = g_aff[side*2+1] + g*64;
    const unsigned* wImg = g_w1h + g*4*4608;

    #pragma unroll 1
    for (int chunk = 0; chunk < 4; chunk++) {
        {
            const float4* src = (const float4*)(wImg + chunk*4608);
            float4* d4 = (float4*)sW;
            for (int e = tid; e < 1152; e += 256) d4[e] = src[e];
        }
        for (int it = tid; it < 1024; it += 256) {
            int p = it & 7, pl = (it >> 3) & 3, j = it >> 5;
            int s = (p < 4) ? 2*p : 2*p - 7;
            int yy = y0 + pl - 1;
            int icA = chunk*16 + 2*p;
            unsigned o0, o1, o2, o3;
            if ((unsigned)yy < 256u) {
                const float* pa = fin + (size_t)icA*HW + yy*256 + x0 + 4*j;
                float4 a = *(const float4*)pa;
                float4 bq = *(const float4*)(pa + HW);
                float ka = a_bn[icA], ba = b_bn[icA];
                float kb = a_bn[icA+1], bb = b_bn[icA+1];
                a.x = fmaf(ka,a.x,ba); a.y = fmaf(ka,a.y,ba);
                a.z = fmaf(ka,a.z,ba); a.w = fmaf(ka,a.w,ba);
                bq.x = fmaf(kb,bq.x,bb); bq.y = fmaf(kb,bq.y,bb);
                bq.z = fmaf(kb,bq.z,bb); bq.w = fmaf(kb,bq.w,bb);
                o0 = h2bits(a.x, bq.x); o1 = h2bits(a.y, bq.y);
                o2 = h2bits(a.z, bq.z); o3 = h2bits(a.w, bq.w);
            } else { o0 = o1 = o2 = o3 = 0u; }
            int base = pl*1064 + (4*j + 1)*8 + s;
            sIn[base] = o0; sIn[base+8] = o1; sIn[base+16] = o2; sIn[base+24] = o3;
        }
        if (tid < 64) {
            int p = tid >> 3, pl = (tid >> 1) & 3, right = tid & 1;
            int s = (p < 4) ? 2*p : 2*p - 7;
            int yy = y0 + pl - 1;
            int xx = right ? x0 + 128 : x0 - 1;
            int col = right ? 129 : 0;
            int icA = chunk*16 + 2*p;
            unsigned o = 0u;
            if ((unsigned)yy < 256u && (unsigned)xx < 256u) {
                size_t off = (size_t)icA*HW + yy*256 + xx;
                float lo = fin[off], hi = fin[off + HW];
                lo = fmaf(a_bn[icA], lo, b_bn[icA]);
                hi = fmaf(a_bn[icA+1], hi, b_bn[icA+1]);
                o = h2bits(lo, hi);
            }
            sIn[pl*1064 + col*8 + s] = o;
        }
        __syncthreads();
        mma_taps(sIn, sW, wset, wrow, wx, r4, c4, acc);
        __syncthreads();
    }

    // epilogue: bias + leaky + channel-pair shfl -> slot-interleaved store
    const float* b1g = b1 + g*64;
    size_t pxrow = ((size_t)(y0 + wrow)*256 + x0 + wx);
    #pragma unroll
    for (int mf = 0; mf < 2; mf++) {
        int oc = wset*32 + mf*16 + r4;
        float bv0 = b1g[oc], bv1 = b1g[oc + 8];
        int chunkc = wset*2 + mf;
        unsigned* cb = g_y2 + 8 + (size_t)((z*4 + g)*4 + chunkc)*524288 + pxrow*8 + r4;
        #pragma unroll
        for (int nf = 0; nf < 8; nf++) {
            float v0 = acc[mf][nf][0] + bv0; v0 = (v0 > 0.f) ? v0 : 0.1f*v0;
            float v1 = acc[mf][nf][1] + bv0; v1 = (v1 > 0.f) ? v1 : 0.1f*v1;
            float v2 = acc[mf][nf][2] + bv1; v2 = (v2 > 0.f) ? v2 : 0.1f*v2;
            float v3 = acc[mf][nf][3] + bv1; v3 = (v3 > 0.f) ? v3 : 0.1f*v3;
            float pv0 = __shfl_xor_sync(~0u, v0, 4);
            float pv1 = __shfl_xor_sync(~0u, v1, 4);
            float pv2 = __shfl_xor_sync(~0u, v2, 4);
            float pv3 = __shfl_xor_sync(~0u, v3, 4);
            unsigned* wp = cb + (nf*8 + 2*c4)*8;
            if ((r4 & 1) == 0) { wp[0] = h2bits(v0, pv0); wp[8] = h2bits(v1, pv1); }
            else               { wp[0] = h2bits(pv2, v2); wp[8] = h2bits(pv3, v3); }
        }
    }
}

// ------------------ conv2 + residual + grouped 1x1 projection ------------------
__global__ __launch_bounds__(256, 2) void conv2proj_kernel(
    const float* __restrict__ cat_l, const float* __restrict__ cat_r,
    const float* __restrict__ b2,
    const float* __restrict__ bq_w, const float* __restrict__ bs_w,
    const float* __restrict__ bq_b, const float* __restrict__ bs_b)
{
    __shared__ __align__(16) unsigned sm[9728];   // conv: sIn 4256 + sW 4608; epi: resbh 9216 + pwh 512
    unsigned* sIn = sm;
    unsigned* sW  = sm + 4256;
    int tile = blockIdx.x, g = blockIdx.y, z = blockIdx.z;
    int side = z >> 1, b = z & 1;
    int y0 = (tile >> 1) * 2, x0 = (tile & 1) * 128;
    int tid = threadIdx.x, lane = tid & 31, warp = tid >> 5;
    int wset = warp >> 2, w4 = warp & 3, wrow = w4 >> 1, wx = (w4 & 1) * 64;
    int r4 = lane >> 2, c4 = lane & 3;

    float acc[2][8][4];
    #pragma unroll
    for (int m = 0; m < 2; m++)
        #pragma unroll
        for (int n = 0; n < 8; n++)
            #pragma unroll
            for (int k = 0; k < 4; k++) acc[m][n][k] = 0.f;

    const unsigned* wImg = g_w2h + g*4*4608;
    int clo = (x0 == 0) ? 1 : 0;
    int chi = (x0 == 0) ? 130 : 129;

    #pragma unroll 1
    for (int chunk = 0; chunk < 4; chunk++) {
        {
            const float4* src = (const float4*)(wImg + chunk*4608);
            float4* d4 = (float4*)sW;
            for (int e = tid; e < 1152; e += 256) d4[e] = src[e];
        }
        // contiguous halo-inclusive copy from slot-interleaved g_y2
        {
            const unsigned* src = g_y2 + 8 + (size_t)((z*4 + g)*4 + chunk)*524288;
            int pl = tid >> 6, lt = tid & 63;
            int yy = y0 + pl - 1;
            bool rowok = (unsigned)yy < 256u;
            const float4* s4 = (const float4*)(src + ((size_t)yy*256 + x0 - 1)*8);
            float4* d4 = (float4*)(sIn + pl*1064);
            for (int f = lt; f < 260; f += 64) {
                int col = f >> 1;
                float4 v = make_float4(0.f, 0.f, 0.f, 0.f);
                if (rowok && col >= clo && col < chi) v = s4[f];
                d4[f] = v;
            }
        }
        __syncthreads();
        mma_taps(sIn, sW, wset, wrow, wx, r4, c4, acc);
        __syncthreads();
    }

    // ---- epilogue: resb = conv2 + b2 + bn(cat) (fp16) -> 1x1 projection mma
    __half* resbh = (__half*)sm;              // [256 px][72 halves]
    unsigned* pwh = sm + 9216;                // [16 oc][32 slot words]
    const float* cat = side ? cat_r : cat_l;
    const float* a_bn = g_aff[side*2] + g*64;
    const float* b_bn = g_aff[side*2+1] + g*64;
    const float* b2g = b2 + g*64;
    const float* pbg = (side ? bs_b : bq_b) + g*16;
    float* qout = (side ? g_K : g_Q) + (size_t)b*CHW1 + (size_t)(g*16)*HW;

    {
        const float* pwsrc = (side ? bs_w : bq_w) + (size_t)(g*16)*64;
        for (int e = tid; e < 512; e += 256) {
            int oc = e >> 5, w5 = e & 31;
            int kc = w5 >> 3, s = w5 & 7;
            int p = (s >> 1) + 4*(s & 1);
            int ic0 = kc*16 + 2*p;
            pwh[e] = h2bits(pwsrc[oc*64 + ic0], pwsrc[oc*64 + ic0 + 1]);
        }
    }
    {
        const float* catb = cat + (size_t)b*CHW4 + (size_t)(g*64)*HW
                          + (size_t)(y0 + wrow)*256 + x0;
        #pragma unroll
        for (int mf = 0; mf < 2; mf++) {
            int ch = wset*32 + mf*16 + r4;
            float bv0 = b2g[ch], bv1 = b2g[ch + 8];
            float a0c = a_bn[ch], b0c = b_bn[ch];
            float a1c = a_bn[ch+8], b1c = b_bn[ch+8];
            #pragma unroll
            for (int nf = 0; nf < 8; nf++) {
                int px = wx + nf*8 + 2*c4;
                int pxl = wrow*128 + px;
                float2 cv0 = *(const float2*)&catb[(size_t)ch*HW + px];
                float2 cv1 = *(const float2*)&catb[(size_t)(ch+8)*HW + px];
                resbh[pxl*72 + ch]       = __float2half_rn(acc[mf][nf][0] + bv0 + fmaf(a0c, cv0.x, b0c));
                resbh[(pxl+1)*72 + ch]   = __float2half_rn(acc[mf][nf][1] + bv0 + fmaf(a0c, cv0.y, b0c));
                resbh[pxl*72 + ch+8]     = __float2half_rn(acc[mf][nf][2] + bv1 + fmaf(a1c, cv1.x, b1c));
                resbh[(pxl+1)*72 + ch+8] = __float2half_rn(acc[mf][nf][3] + bv1 + fmaf(a1c, cv1.y, b1c));
            }
        }
    }
    __syncthreads();
    #pragma unroll
    for (int sb = 0; sb < 2; sb++) {
        int pm = warp*32 + sb*16;
        float PA[2][4];
        #pragma unroll
        for (int nf = 0; nf < 2; nf++) {
            float p0 = pbg[8*nf + 2*c4], p1 = pbg[8*nf + 2*c4 + 1];
            PA[nf][0] = p0; PA[nf][1] = p1; PA[nf][2] = p0; PA[nf][3] = p1;
        }
        #pragma unroll
        for (int kc = 0; kc < 4; kc++) {
            unsigned a0 = *(const unsigned*)&resbh[(pm + r4)*72 + kc*16 + 2*c4];
            unsigned a2 = *(const unsigned*)&resbh[(pm + r4)*72 + kc*16 + 2*c4 + 8];
            unsigned a1 = *(const unsigned*)&resbh[(pm + r4 + 8)*72 + kc*16 + 2*c4];
            unsigned a3 = *(const unsigned*)&resbh[(pm + r4 + 8)*72 + kc*16 + 2*c4 + 8];
            #pragma unroll
            for (int nf = 0; nf < 2; nf++) {
                uint2 bb = *(const uint2*)&pwh[(nf*8 + r4)*32 + kc*8 + 2*c4];
                MMA_F16S(PA[nf], a0, a1, a2, a3, bb.x, bb.y);
            }
        }
        #pragma unroll
        for (int nf = 0; nf < 2; nf++)
            #pragma unroll
            for (int e = 0; e < 2; e++) {
                int oc = 8*nf + 2*c4 + e;
                int pxa = pm + r4, pxb = pxa + 8;
                qout[(size_t)oc*HW + (size_t)(y0 + (pxa >> 7))*256 + x0 + (pxa & 127)] = PA[nf][e];
                qout[(size_t)oc*HW + (size_t)(y0 + (pxb >> 7))*256 + x0 + (pxb & 127)] = PA[nf][2+e];
            }
    }
}

// ------------------ merged transpose-gather (one launch) ------------------
__global__ __launch_bounds__(256) void gather_kernel(
    const float* __restrict__ xl, const float* __restrict__ xr,
    const int* __restrict__ dl, const int* __restrict__ dr)
{
    __shared__ float s[64][113];
    int x0 = blockIdx.x * 64;
    int y  = blockIdx.y;
    int zb = blockIdx.z;
    int b = zb >> 2, which = zb & 3;
    const float* src; float* dst; const int* dvals; int mode;
    switch (which) {
        case 0: src = g_Q; dst = g_GQ;  dvals = dr; mode = 0; break;
        case 1: src = g_K; dst = g_GK;  dvals = dl; mode = 1; break;
        case 2: src = xr;  dst = g_GXR; dvals = dl; mode = 1; break;
        default: src = xl; dst = g_GXL; dvals = dr; mode = 0; break;
    }
    int lo = (mode == 0) ? x0 : max(x0 - 48, 0);
    int t = threadIdx.x;
    const float* sbp = src + (size_t)b*CHW1 + y*256;
    for (int e = t; e < 64*112; e += 256) {
        int c = e / 112, j = e - c*112;
        int col = min(lo + j, 255);
        s[c][j] = sbp[(size_t)c*HW + col];
    }
    __syncthreads();
    float* db = dst + (size_t)b*CHW1 + y*16384 + x0*64;
    const int* dp = dvals + b*HW + y*256;
    for (int e = t; e < 4096; e += 256) {
        int xi = e >> 6, c = e & 63;
        int x = x0 + xi;
        int d = dp[x];
        int sc = (mode == 0) ? min(x + d, 255) : max(x - d, 0);
        db[xi*64 + c] = s[c][sc - lo];
    }
}

// ------------------ per-window attention (fp16 mma) + output assembly ------------------
__global__ __launch_bounds__(128) void attn_kernel(
    const float* __restrict__ xl, const float* __restrict__ xr,
    const int* __restrict__ dl, const int* __restrict__ dr,
    float* __restrict__ out)
{
    __shared__ float sRaw[64][68];
    __shared__ __align__(16) unsigned sA[2048];
    __shared__ __align__(16) unsigned sB[2048];
    __shared__ float mu[8];
    int win = blockIdx.x, side = blockIdx.y, b = blockIdx.z;
    int hi = win >> 5, wi = win & 31;
    int t = threadIdx.x, lane = t & 31, warp = t >> 5;
    int q4 = lane & 3, r4 = lane >> 2;

    const float *Ab, *Bb, *Xb;
    if (side == 0) { Ab = g_Q; Bb = g_GK; Xb = g_GXR; }
    else           { Ab = g_K; Bb = g_GQ; Xb = g_GXL; }
    size_t base = (size_t)b*CHW1 + (size_t)(hi*8)*256 + wi*8;

    for (int e = t; e < 4096; e += 128) {
        int j = e & 63, c = e >> 6;
        sRaw[j][c] = Ab[base + (size_t)c*HW + ((j >> 3)*256 + (j & 7))];
    }
    __syncthreads();
    for (int e = t; e < 2048; e += 128) {
        int i = e >> 5, w5 = e & 31;
        int kc = w5 >> 3, s = w5 & 7;
        int p = (s >> 1) + 4*(s & 1);
        int c0 = kc*16 + 2*p;
        sA[e] = h2bits(sRaw[i][c0], sRaw[i][c0+1]);
    }
    __syncthreads();
    for (int e = t; e < 4096; e += 128) {
        int j = e & 63, c = e >> 6;
        sRaw[j][c] = Bb[base + (size_t)c*HW + ((j >> 3)*256 + (j & 7))];
    }
    __syncthreads();
    {
        int p = t >> 4, sub = t & 15;
        float s = 0.f;
        #pragma unroll 4
        for (int m = 0; m < 32; m++) {
            int el = sub*32 + m;
            s += sRaw[8*p + (el >> 6)][el & 63];
        }
        s += __shfl_xor_sync(~0u, s, 8);
        s += __shfl_xor_sync(~0u, s, 4);
        s += __shfl_xor_sync(~0u, s, 2);
        s += __shfl_xor_sync(~0u, s, 1);
        if (sub == 0) mu[p] = s * (1.f/512.f);
    }
    __syncthreads();
    for (int e = t; e < 2048; e += 128) {
        int j = e >> 5, w5 = e & 31;
        int kc = w5 >> 3, s = w5 & 7;
        int p = (s >> 1) + 4*(s & 1);
        int c0 = kc*16 + 2*p;
        float m = mu[j >> 3];
        sB[e] = h2bits(sRaw[j][c0] - m, sRaw[j][c0+1] - m);
    }
    __syncthreads();

    int m0 = warp * 16;
    float S[8][4];
    #pragma unroll
    for (int nf = 0; nf < 8; nf++)
        #pragma unroll
        for (int k = 0; k < 4; k++) S[nf][k] = 0.f;
    #pragma unroll
    for (int kc = 0; kc < 4; kc++) {
        uint2 alo = *(const uint2*)&sA[(m0 + r4)*32 + kc*8 + q4*2];
        uint2 ahi = *(const uint2*)&sA[(m0 + r4 + 8)*32 + kc*8 + q4*2];
        #pragma unroll
        for (int nf = 0; nf < 8; nf++) {
            uint2 bb = *(const uint2*)&sB[(nf*8 + r4)*32 + kc*8 + q4*2];
            MMA_F16S(S[nf], alo.x, ahi.x, alo.y, ahi.y, bb.x, bb.y);
        }
    }
    float mlo = -1e30f, mhi = -1e30f;
    #pragma unroll
    for (int nf = 0; nf < 8; nf++) {
        mlo = fmaxf(mlo, fmaxf(S[nf][0], S[nf][1]));
        mhi = fmaxf(mhi, fmaxf(S[nf][2], S[nf][3]));
    }
    mlo = fmaxf(mlo, __shfl_xor_sync(~0u, mlo, 1));
    mlo = fmaxf(mlo, __shfl_xor_sync(~0u, mlo, 2));
    mhi = fmaxf(mhi, __shfl_xor_sync(~0u, mhi, 1));
    mhi = fmaxf(mhi, __shfl_xor_sync(~0u, mhi, 2));
    float slo = 0.f, shi = 0.f;
    #pragma unroll
    for (int nf = 0; nf < 8; nf++) {
        S[nf][0] = __expf(S[nf][0] - mlo); S[nf][1] = __expf(S[nf][1] - mlo);
        S[nf][2] = __expf(S[nf][2] - mhi); S[nf][3] = __expf(S[nf][3] - mhi);
        slo += S[nf][0] + S[nf][1];
        shi += S[nf][2] + S[nf][3];
    }
    slo += __shfl_xor_sync(~0u, slo, 1);
    slo += __shfl_xor_sync(~0u, slo, 2);
    shi += __shfl_xor_sync(~0u, shi, 1);
    shi += __shfl_xor_sync(~0u, shi, 2);
    float invlo = 1.f / slo, invhi = 1.f / shi;
    unsigned pa[4][4];
    #pragma unroll
    for (int kc = 0; kc < 4; kc++) {
        pa[kc][0] = h2bits(S[2*kc][0]*invlo,   S[2*kc][1]*invlo);
        pa[kc][1] = h2bits(S[2*kc][2]*invhi,   S[2*kc][3]*invhi);
        pa[kc][2] = h2bits(S[2*kc+1][0]*invlo, S[2*kc+1][1]*invlo);
        pa[kc][3] = h2bits(S[2*kc+1][2]*invhi, S[2*kc+1][3]*invhi);
    }
    __syncthreads();

    for (int e = t; e < 4096; e += 128) {
        int j = e & 63, c = e >> 6;
        sRaw[j][c] = Xb[base + (size_t)c*HW + ((j >> 3)*256 + (j & 7))];
    }
    __syncthreads();
    for (int e = t; e < 2048; e += 128) {
        int c = e >> 5, w5 = e & 31;
        int kc = w5 >> 3, s = w5 & 7;
        int p = (s >> 1) + 4*(s & 1);
        int j0 = kc*16 + 2*p;
        sB[e] = h2bits(sRaw[j0][c], sRaw[j0+1][c]);
    }
    __syncthreads();
    float O[8][4];
    #pragma unroll
    for (int nf = 0; nf < 8; nf++)
        #pragma unroll
        for (int k = 0; k < 4; k++) O[nf][k] = 0.f;
    #pragma unroll
    for (int kc = 0; kc < 4; kc++) {
        #pragma unroll
        for (int nf = 0; nf < 8; nf++) {
            uint2 bb = *(const uint2*)&sB[(nf*8 + r4)*32 + kc*8 + q4*2];
            MMA_F16S(O[nf], pa[kc][0], pa[kc][1], pa[kc][2], pa[kc][3], bb.x, bb.y);
        }
    }
    int ilo = m0 + r4, ihi = ilo + 8;
    int Ylo = hi*8 + (ilo >> 3), Xlo = wi*8 + (ilo & 7);
    int Yhi = hi*8 + (ihi >> 3), Xhi = wi*8 + (ihi & 7);
    const float* xbase = side ? xr : xl;
    float mv_lo, mv_hi;
    if (side == 0) {
        mv_lo = (Xlo - dl[b*HW + Ylo*256 + Xlo] >= 0) ? 1.f : 0.f;
        mv_hi = (Xhi - dl[b*HW + Yhi*256 + Xhi] >= 0) ? 1.f : 0.f;
    } else {
        mv_lo = (Xlo + dr[b*HW + Ylo*256 + Xlo] <= 255) ? 1.f : 0.f;
        mv_hi = (Xhi + dr[b*HW + Yhi*256 + Xhi] <= 255) ? 1.f : 0.f;
    }
    size_t offlo = (size_t)b*CHW1 + Ylo*256 + Xlo;
    size_t offhi = (size_t)b*CHW1 + Yhi*256 + Xhi;
    float* ob = out + (size_t)side*HALF_OUT;
    #pragma unroll
    for (int nf = 0; nf < 8; nf++)
        #pragma unroll
        for (int e = 0; e < 2; e++) {
            size_t go = (size_t)(8*nf + 2*q4 + e) * HW;
            ob[offlo + go] = xbase[offlo + go] + O[nf][e]   * mv_lo;
            ob[offhi + go] = xbase[offhi + go] + O[nf][2+e] * mv_hi;
        }
}

// ------------------ launch ------------------
extern "C" void kernel_launch(void* const* d_in, const int* in_sizes, int n_in,
                              void* d_out, int out_size)
{
    (void)in_sizes; (void)n_in; (void)out_size;
    const float* x_left  = (const float*)d_in[0];
    const float* x_right = (const float*)d_in[1];
    const float* cat_l   = (const float*)d_in[2];
    const float* cat_r   = (const float*)d_in[3];
    const int*   d_left  = (const int*)d_in[4];
    const int*   d_right = (const int*)d_in[5];
    const float* gamma   = (const float*)d_in[6];
    const float* beta    = (const float*)d_in[7];
    const float* rb_w1   = (const float*)d_in[8];
    const float* rb_b1   = (const float*)d_in[9];
    const float* rb_w2   = (const float*)d_in[10];
    const float* rb_b2   = (const float*)d_in[11];
    const float* bq_w    = (const float*)d_in[12];
    const float* bq_b    = (const float*)d_in[13];
    const float* bs_w    = (const float*)d_in[14];
    const float* bs_b    = (const float*)d_in[15];
    float* out = (float*)d_out;

    bn_stats_kernel<<<256, 256>>>(cat_l, gamma, beta, 0);
    bn_stats_kernel<<<256, 256>>>(cat_r, gamma, beta, 1);
    prep_w_kernel<<<dim3(16, 2), 256>>>(rb_w1, rb_w2);

    dim3 cgrid(256, 4, 4);   // 128 y-tiles x 2 x-halves, 4 groups, z = side*2+b
    conv1_kernel    <<<cgrid, 256>>>(cat_l, cat_r, rb_b1);
    conv2proj_kernel<<<cgrid, 256>>>(cat_l, cat_r, rb_b2, bq_w, bs_w, bq_b, bs_b);

    gather_kernel<<<dim3(4, 256, 8), 256>>>(x_left, x_right, d_left, d_right);

    attn_kernel<<<dim3(1024, 2, 2), 128>>>(x_left, x_right, d_left, d_right, out);
}

// round 15
// speedup vs baseline: 1.4743x; 1.4743x over previous
#include <cuda_runtime.h>
#include <cuda_fp16.h>
#include <cstdint>

// Shapes: B=2, C=64, 4C=256, H=W=256, WS=8, hn=wn=32, P=64, DMAX=48
#define HW    65536
#define CHW4  16777216   // 256*65536
#define CHW1  4194304    // 64*65536
#define HALF_OUT 8388608 // 2*64*65536

// ------------------ device scratch (no runtime allocation) ------------------
// conv1 out, slot-interleaved: word idx = 8 + (z*16+g*4+chunk)*524288 + (y*256+x)*8 + s
__device__ __align__(16) unsigned g_y2[8 + 64L*65536*8];
__device__ float g_Q  [2*64*65536];
__device__ float g_K  [2*64*65536];
__device__ __align__(16) __half g_GQh [2*64*65536];   // gather_w(Q, l2r)  flat [b,y,x,c] fp16
__device__ __align__(16) __half g_GKh [2*64*65536];   // gather_w(K, r2l)
__device__ __align__(16) __half g_GXLh[2*64*65536];   // gather_w(x_left, l2r)
__device__ __align__(16) __half g_GXRh[2*64*65536];   // gather_w(x_right, r2l)
__device__ unsigned g_w1h[4*4*4608];   // per (g,chunk): [tap9][oc64][slot8] half2
__device__ unsigned g_w2h[4*4*4608];
__device__ float g_aff[4][256];        // [0]=aL [1]=bL [2]=aR [3]=bR

__device__ __forceinline__ unsigned h2bits(float lo, float hi) {
    __half2 h = __floats2half2_rn(lo, hi);
    return *(unsigned*)&h;
}

#define MMA_F16(d, A0, A1, B)                                               \
    asm volatile("mma.sync.aligned.m16n8k16.row.col.f32.f16.f16.f32 "       \
        "{%0,%1,%2,%3}, {%4,%5,%6,%7}, {%8,%9}, {%0,%1,%2,%3};"             \
        : "+f"((d)[0]), "+f"((d)[1]), "+f"((d)[2]), "+f"((d)[3])            \
        : "r"((A0).x), "r"((A1).x), "r"((A0).y), "r"((A1).y),               \
          "r"((B).x), "r"((B).y))
#define MMA_F16S(d, a0, a1, a2, a3, b0, b1)                                 \
    asm volatile("mma.sync.aligned.m16n8k16.row.col.f32.f16.f16.f32 "       \
        "{%0,%1,%2,%3}, {%4,%5,%6,%7}, {%8,%9}, {%0,%1,%2,%3};"             \
        : "+f"((d)[0]), "+f"((d)[1]), "+f"((d)[2]), "+f"((d)[3])            \
        : "r"(a0), "r"(a1), "r"(a2), "r"(a3), "r"(b0), "r"(b1))

// ------------------ BN batch stats ------------------
__global__ void bn_stats_kernel(const float* __restrict__ cat,
                                const float* __restrict__ gamma,
                                const float* __restrict__ beta, int side)
{
    int ch = blockIdx.x, tid = threadIdx.x;
    const float* p0 = cat + (size_t)ch * HW;
    const float* p1 = cat + (size_t)CHW4 + (size_t)ch * HW;
    double s = 0.0, sq = 0.0;
    for (int e = tid; e < HW; e += 256) {
        float v0 = p0[e], v1 = p1[e];
        s  += (double)v0 + (double)v1;
        sq += (double)v0 * v0 + (double)v1 * v1;
    }
    __shared__ double sh_s[256], sh_q[256];
    sh_s[tid] = s; sh_q[tid] = sq;
    __syncthreads();
    for (int st = 128; st > 0; st >>= 1) {
        if (tid < st) { sh_s[tid] += sh_s[tid+st]; sh_q[tid] += sh_q[tid+st]; }
        __syncthreads();
    }
    if (tid == 0) {
        double n = 131072.0;
        double mu  = sh_s[0] / n;
        double var = sh_q[0] / n - mu * mu;
        float a = gamma[ch] * rsqrtf((float)var + 1e-5f);
        g_aff[side*2][ch]   = a;
        g_aff[side*2+1][ch] = beta[ch] - a * (float)mu;
    }
}

// ------------------ weight prep ------------------
__global__ void prep_w_kernel(const float* __restrict__ w1, const float* __restrict__ w2)
{
    int gc = blockIdx.x;            // g*4 + chunk
    int layer = blockIdx.y;
    const float* w = layer ? w2 : w1;
    unsigned* dst = (layer ? g_w2h : g_w1h) + gc * 4608;
    int g = gc >> 2, chunk = gc & 3;
    for (int e = threadIdx.x; e < 4608; e += 256) {
        int tap = e >> 9, oc = (e >> 3) & 63, s = e & 7;
        int p = (s >> 1) + 4*(s & 1);
        int ic = chunk*16 + 2*p;
        int o = g*64 + oc;
        dst[e] = h2bits(w[(o*64 + ic)*9 + tap], w[(o*64 + ic + 1)*9 + tap]);
    }
}

// ------------------ MMA tap loop: 2mf x 8nf per warp ------------------
__device__ __forceinline__ void mma_taps(const unsigned* sIn, const unsigned* sW,
    int wset, int wrow, int wx, int r4, int c4, float acc[2][8][4])
{
    #pragma unroll
    for (int tap = 0; tap < 9; tap++) {
        const int dy = tap / 3, dx = tap - dy*3;
        const unsigned* wB = sW + tap*512;
        uint2 A0[2], A1[2];
        #pragma unroll
        for (int mf = 0; mf < 2; mf++) {
            int oc0 = wset*32 + mf*16 + r4;
            A0[mf] = *(const uint2*)(wB + oc0*8 + 2*c4);
            A1[mf] = *(const uint2*)(wB + (oc0 + 8)*8 + 2*c4);
        }
        const unsigned* bp = sIn + (wrow + dy)*1064 + (wx + dx + r4)*8 + 2*c4;
        #pragma unroll
        for (int nf = 0; nf < 8; nf++) {
            uint2 Bf = *(const uint2*)(bp + nf*64);
            MMA_F16(acc[0][nf], A0[0], A1[0], Bf);
            MMA_F16(acc[1][nf], A0[1], A1[1], Bf);
        }
    }
}

// ------------------ conv1: slot-interleaved fp16 out ------------------
__global__ __launch_bounds__(256, 2) void conv1_kernel(
    const float* __restrict__ cat_l, const float* __restrict__ cat_r,
    const float* __restrict__ b1)
{
    __shared__ __align__(16) unsigned sm[8864];   // sIn 4256 + sW 4608
    unsigned* sIn = sm;
    unsigned* sW  = sm + 4256;
    int tile = blockIdx.x, g = blockIdx.y, z = blockIdx.z;
    int side = z >> 1, b = z & 1;
    int y0 = (tile >> 1) * 2, x0 = (tile & 1) * 128;
    int tid = threadIdx.x, lane = tid & 31, warp = tid >> 5;
    int wset = warp >> 2, w4 = warp & 3, wrow = w4 >> 1, wx = (w4 & 1) * 64;
    int r4 = lane >> 2, c4 = lane & 3;

    float acc[2][8][4];
    #pragma unroll
    for (int m = 0; m < 2; m++)
        #pragma unroll
        for (int n = 0; n < 8; n++)
            #pragma unroll
            for (int k = 0; k < 4; k++) acc[m][n][k] = 0.f;

    const float* cat = side ? cat_r : cat_l;
    const float* fin = cat + (size_t)b*CHW4 + (size_t)(g*64)*HW;
    const float* a_bn = g_aff[side*2] + g*64;
    const float* b_bn = g_aff[side*2+1] + g*64;
    const unsigned* wImg = g_w1h + g*4*4608;

    #pragma unroll 1
    for (int chunk = 0; chunk < 4; chunk++) {
        {
            const float4* src = (const float4*)(wImg + chunk*4608);
            float4* d4 = (float4*)sW;
            for (int e = tid; e < 1152; e += 256) d4[e] = src[e];
        }
        for (int it = tid; it < 1024; it += 256) {
            int p = it & 7, pl = (it >> 3) & 3, j = it >> 5;
            int s = (p < 4) ? 2*p : 2*p - 7;
            int yy = y0 + pl - 1;
            int icA = chunk*16 + 2*p;
            unsigned o0, o1, o2, o3;
            if ((unsigned)yy < 256u) {
                const float* pa = fin + (size_t)icA*HW + yy*256 + x0 + 4*j;
                float4 a = *(const float4*)pa;
                float4 bq = *(const float4*)(pa + HW);
                float ka = a_bn[icA], ba = b_bn[icA];
                float kb = a_bn[icA+1], bb = b_bn[icA+1];
                a.x = fmaf(ka,a.x,ba); a.y = fmaf(ka,a.y,ba);
                a.z = fmaf(ka,a.z,ba); a.w = fmaf(ka,a.w,ba);
                bq.x = fmaf(kb,bq.x,bb); bq.y = fmaf(kb,bq.y,bb);
                bq.z = fmaf(kb,bq.z,bb); bq.w = fmaf(kb,bq.w,bb);
                o0 = h2bits(a.x, bq.x); o1 = h2bits(a.y, bq.y);
                o2 = h2bits(a.z, bq.z); o3 = h2bits(a.w, bq.w);
            } else { o0 = o1 = o2 = o3 = 0u; }
            int base = pl*1064 + (4*j + 1)*8 + s;
            sIn[base] = o0; sIn[base+8] = o1; sIn[base+16] = o2; sIn[base+24] = o3;
        }
        if (tid < 64) {
            int p = tid >> 3, pl = (tid >> 1) & 3, right = tid & 1;
            int s = (p < 4) ? 2*p : 2*p - 7;
            int yy = y0 + pl - 1;
            int xx = right ? x0 + 128 : x0 - 1;
            int col = right ? 129 : 0;
            int icA = chunk*16 + 2*p;
            unsigned o = 0u;
            if ((unsigned)yy < 256u && (unsigned)xx < 256u) {
                size_t off = (size_t)icA*HW + yy*256 + xx;
                float lo = fin[off], hi = fin[off + HW];
                lo = fmaf(a_bn[icA], lo, b_bn[icA]);
                hi = fmaf(a_bn[icA+1], hi, b_bn[icA+1]);
                o = h2bits(lo, hi);
            }
            sIn[pl*1064 + col*8 + s] = o;
        }
        __syncthreads();
        mma_taps(sIn, sW, wset, wrow, wx, r4, c4, acc);
        __syncthreads();
    }

    // epilogue: bias + leaky + channel-pair shfl -> slot-interleaved store
    const float* b1g = b1 + g*64;
    size_t pxrow = ((size_t)(y0 + wrow)*256 + x0 + wx);
    #pragma unroll
    for (int mf = 0; mf < 2; mf++) {
        int oc = wset*32 + mf*16 + r4;
        float bv0 = b1g[oc], bv1 = b1g[oc + 8];
        int chunkc = wset*2 + mf;
        unsigned* cb = g_y2 + 8 + (size_t)((z*4 + g)*4 + chunkc)*524288 + pxrow*8 + r4;
        #pragma unroll
        for (int nf = 0; nf < 8; nf++) {
            float v0 = acc[mf][nf][0] + bv0; v0 = (v0 > 0.f) ? v0 : 0.1f*v0;
            float v1 = acc[mf][nf][1] + bv0; v1 = (v1 > 0.f) ? v1 : 0.1f*v1;
            float v2 = acc[mf][nf][2] + bv1; v2 = (v2 > 0.f) ? v2 : 0.1f*v2;
            float v3 = acc[mf][nf][3] + bv1; v3 = (v3 > 0.f) ? v3 : 0.1f*v3;
            float pv0 = __shfl_xor_sync(~0u, v0, 4);
            float pv1 = __shfl_xor_sync(~0u, v1, 4);
            float pv2 = __shfl_xor_sync(~0u, v2, 4);
            float pv3 = __shfl_xor_sync(~0u, v3, 4);
            unsigned* wp = cb + (nf*8 + 2*c4)*8;
            if ((r4 & 1) == 0) { wp[0] = h2bits(v0, pv0); wp[8] = h2bits(v1, pv1); }
            else               { wp[0] = h2bits(pv2, v2); wp[8] = h2bits(pv3, v3); }
        }
    }
}

// ------------------ conv2 + residual + grouped 1x1 projection ------------------
__global__ __launch_bounds__(256, 2) void conv2proj_kernel(
    const float* __restrict__ cat_l, const float* __restrict__ cat_r,
    const float* __restrict__ b2,
    const float* __restrict__ bq_w, const float* __restrict__ bs_w,
    const float* __restrict__ bq_b, const float* __restrict__ bs_b)
{
    __shared__ __align__(16) unsigned sm[9728];   // conv: sIn 4256 + sW 4608; epi: resbh 9216 + pwh 512
    unsigned* sIn = sm;
    unsigned* sW  = sm + 4256;
    int tile = blockIdx.x, g = blockIdx.y, z = blockIdx.z;
    int side = z >> 1, b = z & 1;
    int y0 = (tile >> 1) * 2, x0 = (tile & 1) * 128;
    int tid = threadIdx.x, lane = tid & 31, warp = tid >> 5;
    int wset = warp >> 2, w4 = warp & 3, wrow = w4 >> 1, wx = (w4 & 1) * 64;
    int r4 = lane >> 2, c4 = lane & 3;

    float acc[2][8][4];
    #pragma unroll
    for (int m = 0; m < 2; m++)
        #pragma unroll
        for (int n = 0; n < 8; n++)
            #pragma unroll
            for (int k = 0; k < 4; k++) acc[m][n][k] = 0.f;

    const unsigned* wImg = g_w2h + g*4*4608;
    int clo = (x0 == 0) ? 1 : 0;
    int chi = (x0 == 0) ? 130 : 129;

    #pragma unroll 1
    for (int chunk = 0; chunk < 4; chunk++) {
        {
            const float4* src = (const float4*)(wImg + chunk*4608);
            float4* d4 = (float4*)sW;
            for (int e = tid; e < 1152; e += 256) d4[e] = src[e];
        }
        // contiguous halo-inclusive copy from slot-interleaved g_y2
        {
            const unsigned* src = g_y2 + 8 + (size_t)((z*4 + g)*4 + chunk)*524288;
            int pl = tid >> 6, lt = tid & 63;
            int yy = y0 + pl - 1;
            bool rowok = (unsigned)yy < 256u;
            const float4* s4 = (const float4*)(src + ((size_t)yy*256 + x0 - 1)*8);
            float4* d4 = (float4*)(sIn + pl*1064);
            for (int f = lt; f < 260; f += 64) {
                int col = f >> 1;
                float4 v = make_float4(0.f, 0.f, 0.f, 0.f);
                if (rowok && col >= clo && col < chi) v = s4[f];
                d4[f] = v;
            }
        }
        __syncthreads();
        mma_taps(sIn, sW, wset, wrow, wx, r4, c4, acc);
        __syncthreads();
    }

    // ---- epilogue: resb = conv2 + b2 + bn(cat) (fp16) -> 1x1 projection mma
    __half* resbh = (__half*)sm;              // [256 px][72 halves]
    unsigned* pwh = sm + 9216;                // [16 oc][32 slot words]
    const float* cat = side ? cat_r : cat_l;
    const float* a_bn = g_aff[side*2] + g*64;
    const float* b_bn = g_aff[side*2+1] + g*64;
    const float* b2g = b2 + g*64;
    const float* pbg = (side ? bs_b : bq_b) + g*16;
    float* qout = (side ? g_K : g_Q) + (size_t)b*CHW1 + (size_t)(g*16)*HW;

    {
        const float* pwsrc = (side ? bs_w : bq_w) + (size_t)(g*16)*64;
        for (int e = tid; e < 512; e += 256) {
            int oc = e >> 5, w5 = e & 31;
            int kc = w5 >> 3, s = w5 & 7;
            int p = (s >> 1) + 4*(s & 1);
            int ic0 = kc*16 + 2*p;
            pwh[e] = h2bits(pwsrc[oc*64 + ic0], pwsrc[oc*64 + ic0 + 1]);
        }
    }
    {
        const float* catb = cat + (size_t)b*CHW4 + (size_t)(g*64)*HW
                          + (size_t)(y0 + wrow)*256 + x0;
        #pragma unroll
        for (int mf = 0; mf < 2; mf++) {
            int ch = wset*32 + mf*16 + r4;
            float bv0 = b2g[ch], bv1 = b2g[ch + 8];
            float a0c = a_bn[ch], b0c = b_bn[ch];
            float a1c = a_bn[ch+8], b1c = b_bn[ch+8];
            #pragma unroll
            for (int nf = 0; nf < 8; nf++) {
                int px = wx + nf*8 + 2*c4;
                int pxl = wrow*128 + px;
                float2 cv0 = *(const float2*)&catb[(size_t)ch*HW + px];
                float2 cv1 = *(const float2*)&catb[(size_t)(ch+8)*HW + px];
                resbh[pxl*72 + ch]       = __float2half_rn(acc[mf][nf][0] + bv0 + fmaf(a0c, cv0.x, b0c));
                resbh[(pxl+1)*72 + ch]   = __float2half_rn(acc[mf][nf][1] + bv0 + fmaf(a0c, cv0.y, b0c));
                resbh[pxl*72 + ch+8]     = __float2half_rn(acc[mf][nf][2] + bv1 + fmaf(a1c, cv1.x, b1c));
                resbh[(pxl+1)*72 + ch+8] = __float2half_rn(acc[mf][nf][3] + bv1 + fmaf(a1c, cv1.y, b1c));
            }
        }
    }
    __syncthreads();
    #pragma unroll
    for (int sb = 0; sb < 2; sb++) {
        int pm = warp*32 + sb*16;
        float PA[2][4];
        #pragma unroll
        for (int nf = 0; nf < 2; nf++) {
            float p0 = pbg[8*nf + 2*c4], p1 = pbg[8*nf + 2*c4 + 1];
            PA[nf][0] = p0; PA[nf][1] = p1; PA[nf][2] = p0; PA[nf][3] = p1;
        }
        #pragma unroll
        for (int kc = 0; kc < 4; kc++) {
            unsigned a0 = *(const unsigned*)&resbh[(pm + r4)*72 + kc*16 + 2*c4];
            unsigned a2 = *(const unsigned*)&resbh[(pm + r4)*72 + kc*16 + 2*c4 + 8];
            unsigned a1 = *(const unsigned*)&resbh[(pm + r4 + 8)*72 + kc*16 + 2*c4];
            unsigned a3 = *(const unsigned*)&resbh[(pm + r4 + 8)*72 + kc*16 + 2*c4 + 8];
            #pragma unroll
            for (int nf = 0; nf < 2; nf++) {
                uint2 bb = *(const uint2*)&pwh[(nf*8 + r4)*32 + kc*8 + 2*c4];
                MMA_F16S(PA[nf], a0, a1, a2, a3, bb.x, bb.y);
            }
        }
        #pragma unroll
        for (int nf = 0; nf < 2; nf++)
            #pragma unroll
            for (int e = 0; e < 2; e++) {
                int oc = 8*nf + 2*c4 + e;
                int pxa = pm + r4, pxb = pxa + 8;
                qout[(size_t)oc*HW + (size_t)(y0 + (pxa >> 7))*256 + x0 + (pxa & 127)] = PA[nf][e];
                qout[(size_t)oc*HW + (size_t)(y0 + (pxb >> 7))*256 + x0 + (pxb & 127)] = PA[nf][2+e];
            }
    }
}

// ------------------ merged transpose-gather (one launch, fp16 output) ------------------
__global__ __launch_bounds__(256) void gather_kernel(
    const float* __restrict__ xl, const float* __restrict__ xr,
    const int* __restrict__ dl, const int* __restrict__ dr)
{
    __shared__ float s[64][113];
    int x0 = blockIdx.x * 64;
    int y  = blockIdx.y;
    int zb = blockIdx.z;
    int b = zb >> 2, which = zb & 3;
    const float* src; __half* dst; const int* dvals; int mode;
    switch (which) {
        case 0: src = g_Q; dst = g_GQh;  dvals = dr; mode = 0; break;
        case 1: src = g_K; dst = g_GKh;  dvals = dl; mode = 1; break;
        case 2: src = xr;  dst = g_GXRh; dvals = dl; mode = 1; break;
        default: src = xl; dst = g_GXLh; dvals = dr; mode = 0; break;
    }
    int lo = (mode == 0) ? x0 : max(x0 - 48, 0);
    int t = threadIdx.x;
    const float* sbp = src + (size_t)b*CHW1 + y*256;
    for (int e = t; e < 64*112; e += 256) {
        int c = e / 112, j = e - c*112;
        int col = min(lo + j, 255);
        s[c][j] = sbp[(size_t)c*HW + col];
    }
    __syncthreads();
    __half* db = dst + (size_t)b*CHW1 + y*16384 + x0*64;
    const int* dp = dvals + b*HW + y*256;
    for (int e = t; e < 4096; e += 256) {
        int xi = e >> 6, c = e & 63;
        int x = x0 + xi;
        int d = dp[x];
        int sc = (mode == 0) ? min(x + d, 255) : max(x - d, 0);
        db[xi*64 + c] = __float2half_rn(s[c][sc - lo]);
    }
}

// ------------------ per-window attention (fp16 mma) + output assembly ------------------
__global__ __launch_bounds__(128) void attn_kernel(
    const float* __restrict__ xl, const float* __restrict__ xr,
    const int* __restrict__ dl, const int* __restrict__ dr,
    float* __restrict__ out)
{
    __shared__ float sRaw[64][68];
    __shared__ __align__(16) unsigned sA[2048];
    __shared__ __align__(16) unsigned sB[2048];
    __shared__ float mu[8];
    int win = blockIdx.x, side = blockIdx.y, b = blockIdx.z;
    int hi = win >> 5, wi = win & 31;
    int t = threadIdx.x, lane = t & 31, warp = t >> 5;
    int q4 = lane & 3, r4 = lane >> 2;

    const float* Ab;
    const __half *Bb, *Xb;
    if (side == 0) { Ab = g_Q; Bb = g_GKh; Xb = g_GXRh; }
    else           { Ab = g_K; Bb = g_GQh; Xb = g_GXLh; }
    size_t base = (size_t)b*CHW1 + (size_t)(hi*8)*256 + wi*8;

    for (int e = t; e < 4096; e += 128) {
        int j = e & 63, c = e >> 6;
        sRaw[j][c] = Ab[base + (size_t)c*HW + ((j >> 3)*256 + (j & 7))];
    }
    __syncthreads();
    for (int e = t; e < 2048; e += 128) {
        int i = e >> 5, w5 = e & 31;
        int kc = w5 >> 3, s = w5 & 7;
        int p = (s >> 1) + 4*(s & 1);
        int c0 = kc*16 + 2*p;
        sA[e] = h2bits(sRaw[i][c0], sRaw[i][c0+1]);
    }
    __syncthreads();
    for (int e = t; e < 4096; e += 128) {
        int j = e & 63, c = e >> 6;
        sRaw[j][c] = __half2float(Bb[base + (size_t)c*HW + ((j >> 3)*256 + (j & 7))]);
    }
    __syncthreads();
    {
        int p = t >> 4, sub = t & 15;
        float s = 0.f;
        #pragma unroll 4
        for (int m = 0; m < 32; m++) {
            int el = sub*32 + m;
            s += sRaw[8*p + (el >> 6)][el & 63];
        }
        s += __shfl_xor_sync(~0u, s, 8);
        s += __shfl_xor_sync(~0u, s, 4);
        s += __shfl_xor_sync(~0u, s, 2);
        s += __shfl_xor_sync(~0u, s, 1);
        if (sub == 0) mu[p] = s * (1.f/512.f);
    }
    __syncthreads();
    for (int e = t; e < 2048; e += 128) {
        int j = e >> 5, w5 = e & 31;
        int kc = w5 >> 3, s = w5 & 7;
        int p = (s >> 1) + 4*(s & 1);
        int c0 = kc*16 + 2*p;
        float m = mu[j >> 3];
        sB[e] = h2bits(sRaw[j][c0] - m, sRaw[j][c0+1] - m);
    }
    __syncthreads();

    int m0 = warp * 16;
    float S[8][4];
    #pragma unroll
    for (int nf = 0; nf < 8; nf++)
        #pragma unroll
        for (int k = 0; k < 4; k++) S[nf][k] = 0.f;
    #pragma unroll
    for (int kc = 0; kc < 4; kc++) {
        uint2 alo = *(const uint2*)&sA[(m0 + r4)*32 + kc*8 + q4*2];
        uint2 ahi = *(const uint2*)&sA[(m0 + r4 + 8)*32 + kc*8 + q4*2];
        #pragma unroll
        for (int nf = 0; nf < 8; nf++) {
            uint2 bb = *(const uint2*)&sB[(nf*8 + r4)*32 + kc*8 + q4*2];
            MMA_F16S(S[nf], alo.x, ahi.x, alo.y, ahi.y, bb.x, bb.y);
        }
    }
    float mlo = -1e30f, mhi = -1e30f;
    #pragma unroll
    for (int nf = 0; nf < 8; nf++) {
        mlo = fmaxf(mlo, fmaxf(S[nf][0], S[nf][1]));
        mhi = fmaxf(mhi, fmaxf(S[nf][2], S[nf][3]));
    }
    mlo = fmaxf(mlo, __shfl_xor_sync(~0u, mlo, 1));
    mlo = fmaxf(mlo, __shfl_xor_sync(~0u, mlo, 2));
    mhi = fmaxf(mhi, __shfl_xor_sync(~0u, mhi, 1));
    mhi = fmaxf(mhi, __shfl_xor_sync(~0u, mhi, 2));
    float slo = 0.f, shi = 0.f;
    #pragma unroll
    for (int nf = 0; nf < 8; nf++) {
        S[nf][0] = __expf(S[nf][0] - mlo); S[nf][1] = __expf(S[nf][1] - mlo);
        S[nf][2] = __expf(S[nf][2] - mhi); S[nf][3] = __expf(S[nf][3] - mhi);
        slo += S[nf][0] + S[nf][1];
        shi += S[nf][2] + S[nf][3];
    }
    slo += __shfl_xor_sync(~0u, slo, 1);
    slo += __shfl_xor_sync(~0u, slo, 2);
    shi += __shfl_xor_sync(~0u, shi, 1);
    shi += __shfl_xor_sync(~0u, shi, 2);
    float invlo = 1.f / slo, invhi = 1.f / shi;
    unsigned pa[4][4];
    #pragma unroll
    for (int kc = 0; kc < 4; kc++) {
        pa[kc][0] = h2bits(S[2*kc][0]*invlo,   S[2*kc][1]*invlo);
        pa[kc][1] = h2bits(S[2*kc][2]*invhi,   S[2*kc][3]*invhi);
        pa[kc][2] = h2bits(S[2*kc+1][0]*invlo, S[2*kc+1][1]*invlo);
        pa[kc][3] = h2bits(S[2*kc+1][2]*invhi, S[2*kc+1][3]*invhi);
    }
    __syncthreads();

    for (int e = t; e < 4096; e += 128) {
        int j = e & 63, c = e >> 6;
        sRaw[j][c] = __half2float(Xb[base + (size_t)c*HW + ((j >> 3)*256 + (j & 7))]);
    }
    __syncthreads();
    for (int e = t; e < 2048; e += 128) {
        int c = e >> 5, w5 = e & 31;
        int kc = w5 >> 3, s = w5 & 7;
        int p = (s >> 1) + 4*(s & 1);
        int j0 = kc*16 + 2*p;
        sB[e] = h2bits(sRaw[j0][c], sRaw[j0+1][c]);
    }
    __syncthreads();
    float O[8][4];
    #pragma unroll
    for (int nf = 0; nf < 8; nf++)
        #pragma unroll
        for (int k = 0; k < 4; k++) O[nf][k] = 0.f;
    #pragma unroll
    for (int kc = 0; kc < 4; kc++) {
        #pragma unroll
        for (int nf = 0; nf < 8; nf++) {
            uint2 bb = *(const uint2*)&sB[(nf*8 + r4)*32 + kc*8 + q4*2];
            MMA_F16S(O[nf], pa[kc][0], pa[kc][1], pa[kc][2], pa[kc][3], bb.x, bb.y);
        }
    }
    int ilo = m0 + r4, ihi = ilo + 8;
    int Ylo = hi*8 + (ilo >> 3), Xlo = wi*8 + (ilo & 7);
    int Yhi = hi*8 + (ihi >> 3), Xhi = wi*8 + (ihi & 7);
    const float* xbase = side ? xr : xl;
    float mv_lo, mv_hi;
    if (side == 0) {
        mv_lo = (Xlo - dl[b*HW + Ylo*256 + Xlo] >= 0) ? 1.f : 0.f;
        mv_hi = (Xhi - dl[b*HW + Yhi*256 + Xhi] >= 0) ? 1.f : 0.f;
    } else {
        mv_lo = (Xlo + dr[b*HW + Ylo*256 + Xlo] <= 255) ? 1.f : 0.f;
        mv_hi = (Xhi + dr[b*HW + Yhi*256 + Xhi] <= 255) ? 1.f : 0.f;
    }
    size_t offlo = (size_t)b*CHW1 + Ylo*256 + Xlo;
    size_t offhi = (size_t)b*CHW1 + Yhi*256 + Xhi;
    float* ob = out + (size_t)side*HALF_OUT;
    #pragma unroll
    for (int nf = 0; nf < 8; nf++)
        #pragma unroll
        for (int e = 0; e < 2; e++) {
            size_t go = (size_t)(8*nf + 2*q4 + e) * HW;
            ob[offlo + go] = xbase[offlo + go] + O[nf][e]   * mv_lo;
            ob[offhi + go] = xbase[offhi + go] + O[nf][2+e] * mv_hi;
        }
}

// ------------------ launch ------------------
extern "C" void kernel_launch(void* const* d_in, const int* in_sizes, int n_in,
                              void* d_out, int out_size)
{
    (void)in_sizes; (void)n_in; (void)out_size;
    const float* x_left  = (const float*)d_in[0];
    const float* x_right = (const float*)d_in[1];
    const float* cat_l   = (const float*)d_in[2];
    const float* cat_r   = (const float*)d_in[3];
    const int*   d_left  = (const int*)d_in[4];
    const int*   d_right = (const int*)d_in[5];
    const float* gamma   = (const float*)d_in[6];
    const float* beta    = (const float*)d_in[7];
    const float* rb_w1   = (const float*)d_in[8];
    const float* rb_b1   = (const float*)d_in[9];
    const float* rb_w2   = (const float*)d_in[10];
    const float* rb_b2   = (const float*)d_in[11];
    const float* bq_w    = (const float*)d_in[12];
    const float* bq_b    = (const float*)d_in[13];
    const float* bs_w    = (const float*)d_in[14];
    const float* bs_b    = (const float*)d_in[15];
    float* out = (float*)d_out;

    bn_stats_kernel<<<256, 256>>>(cat_l, gamma, beta, 0);
    bn_stats_kernel<<<256, 256>>>(cat_r, gamma, beta, 1);
    prep_w_kernel<<<dim3(16, 2), 256>>>(rb_w1, rb_w2);

    dim3 cgrid(256, 4, 4);   // 128 y-tiles x 2 x-halves, 4 groups, z = side*2+b
    conv1_kernel    <<<cgrid, 256>>>(cat_l, cat_r, rb_b1);
    conv2proj_kernel<<<cgrid, 256>>>(cat_l, cat_r, rb_b2, bq_w, bs_w, bq_b, bs_b);

    gather_kernel<<<dim3(4, 256, 8), 256>>>(x_left, x_right, d_left, d_right);

    attn_kernel<<<dim3(1024, 2, 2), 128>>>(x_left, x_right, d_left, d_right, out);
}

// round 16
// speedup vs baseline: 1.4869x; 1.0085x over previous
#include <cuda_runtime.h>
#include <cuda_fp16.h>
#include <cstdint>

// Shapes: B=2, C=64, 4C=256, H=W=256, WS=8, hn=wn=32, P=64, DMAX=48
#define HW    65536
#define CHW4  16777216   // 256*65536
#define CHW1  4194304    // 64*65536
#define HALF_OUT 8388608 // 2*64*65536

// ------------------ device scratch (no runtime allocation) ------------------
// conv1 out, slot-interleaved: word idx = 8 + (z*16+g*4+chunk)*524288 + (y*256+x)*8 + s
__device__ __align__(16) unsigned g_y2[8 + 64L*65536*8];
__device__ __align__(16) __half g_Qh [2*64*65536];    // Q (fp16)
__device__ __align__(16) __half g_Kh [2*64*65536];    // K (fp16)
__device__ __align__(16) __half g_GQh [2*64*65536];   // gather_w(Q, l2r)  flat [b,y,x,c] fp16
__device__ __align__(16) __half g_GKh [2*64*65536];   // gather_w(K, r2l)
__device__ __align__(16) __half g_GXLh[2*64*65536];   // gather_w(x_left, l2r)
__device__ __align__(16) __half g_GXRh[2*64*65536];   // gather_w(x_right, r2l)
__device__ unsigned g_w1h[4*4*4608];   // per (g,chunk): [tap9][oc64][slot8] half2
__device__ unsigned g_w2h[4*4*4608];
__device__ float g_aff[4][256];        // [0]=aL [1]=bL [2]=aR [3]=bR

__device__ __forceinline__ unsigned h2bits(float lo, float hi) {
    __half2 h = __floats2half2_rn(lo, hi);
    return *(unsigned*)&h;
}

#define MMA_F16(d, A0, A1, B)                                               \
    asm volatile("mma.sync.aligned.m16n8k16.row.col.f32.f16.f16.f32 "       \
        "{%0,%1,%2,%3}, {%4,%5,%6,%7}, {%8,%9}, {%0,%1,%2,%3};"             \
        : "+f"((d)[0]), "+f"((d)[1]), "+f"((d)[2]), "+f"((d)[3])            \
        : "r"((A0).x), "r"((A1).x), "r"((A0).y), "r"((A1).y),               \
          "r"((B).x), "r"((B).y))
#define MMA_F16S(d, a0, a1, a2, a3, b0, b1)                                 \
    asm volatile("mma.sync.aligned.m16n8k16.row.col.f32.f16.f16.f32 "       \
        "{%0,%1,%2,%3}, {%4,%5,%6,%7}, {%8,%9}, {%0,%1,%2,%3};"             \
        : "+f"((d)[0]), "+f"((d)[1]), "+f"((d)[2]), "+f"((d)[3])            \
        : "r"(a0), "r"(a1), "r"(a2), "r"(a3), "r"(b0), "r"(b1))

// ------------------ BN batch stats ------------------
__global__ void bn_stats_kernel(const float* __restrict__ cat,
                                const float* __restrict__ gamma,
                                const float* __restrict__ beta, int side)
{
    int ch = blockIdx.x, tid = threadIdx.x;
    const float* p0 = cat + (size_t)ch * HW;
    const float* p1 = cat + (size_t)CHW4 + (size_t)ch * HW;
    double s = 0.0, sq = 0.0;
    for (int e = tid; e < HW; e += 256) {
        float v0 = p0[e], v1 = p1[e];
        s  += (double)v0 + (double)v1;
        sq += (double)v0 * v0 + (double)v1 * v1;
    }
    __shared__ double sh_s[256], sh_q[256];
    sh_s[tid] = s; sh_q[tid] = sq;
    __syncthreads();
    for (int st = 128; st > 0; st >>= 1) {
        if (tid < st) { sh_s[tid] += sh_s[tid+st]; sh_q[tid] += sh_q[tid+st]; }
        __syncthreads();
    }
    if (tid == 0) {
        double n = 131072.0;
        double mu  = sh_s[0] / n;
        double var = sh_q[0] / n - mu * mu;
        float a = gamma[ch] * rsqrtf((float)var + 1e-5f);
        g_aff[side*2][ch]   = a;
        g_aff[side*2+1][ch] = beta[ch] - a * (float)mu;
    }
}

// ------------------ weight prep ------------------
__global__ void prep_w_kernel(const float* __restrict__ w1, const float* __restrict__ w2)
{
    int gc = blockIdx.x;            // g*4 + chunk
    int layer = blockIdx.y;
    const float* w = layer ? w2 : w1;
    unsigned* dst = (layer ? g_w2h : g_w1h) + gc * 4608;
    int g = gc >> 2, chunk = gc & 3;
    for (int e = threadIdx.x; e < 4608; e += 256) {
        int tap = e >> 9, oc = (e >> 3) & 63, s = e & 7;
        int p = (s >> 1) + 4*(s & 1);
        int ic = chunk*16 + 2*p;
        int o = g*64 + oc;
        dst[e] = h2bits(w[(o*64 + ic)*9 + tap], w[(o*64 + ic + 1)*9 + tap]);
    }
}

// ------------------ MMA tap loop: 2mf x 8nf per warp ------------------
__device__ __forceinline__ void mma_taps(const unsigned* sIn, const unsigned* sW,
    int wset, int wrow, int wx, int r4, int c4, float acc[2][8][4])
{
    #pragma unroll
    for (int tap = 0; tap < 9; tap++) {
        const int dy = tap / 3, dx = tap - dy*3;
        const unsigned* wB = sW + tap*512;
        uint2 A0[2], A1[2];
        #pragma unroll
        for (int mf = 0; mf < 2; mf++) {
            int oc0 = wset*32 + mf*16 + r4;
            A0[mf] = *(const uint2*)(wB + oc0*8 + 2*c4);
            A1[mf] = *(const uint2*)(wB + (oc0 + 8)*8 + 2*c4);
        }
        const unsigned* bp = sIn + (wrow + dy)*1064 + (wx + dx + r4)*8 + 2*c4;
        #pragma unroll
        for (int nf = 0; nf < 8; nf++) {
            uint2 Bf = *(const uint2*)(bp + nf*64);
            MMA_F16(acc[0][nf], A0[0], A1[0], Bf);
            MMA_F16(acc[1][nf], A0[1], A1[1], Bf);
        }
    }
}

// ------------------ conv1: slot-interleaved fp16 out ------------------
__global__ __launch_bounds__(256, 2) void conv1_kernel(
    const float* __restrict__ cat_l, const float* __restrict__ cat_r,
    const float* __restrict__ b1)
{
    __shared__ __align__(16) unsigned sm[8864];   // sIn 4256 + sW 4608
    unsigned* sIn = sm;
    unsigned* sW  = sm + 4256;
    int tile = blockIdx.x, g = blockIdx.y, z = blockIdx.z;
    int side = z >> 1, b = z & 1;
    int y0 = (tile >> 1) * 2, x0 = (tile & 1) * 128;
    int tid = threadIdx.x, lane = tid & 31, warp = tid >> 5;
    int wset = warp >> 2, w4 = warp & 3, wrow = w4 >> 1, wx = (w4 & 1) * 64;
    int r4 = lane >> 2, c4 = lane & 3;

    float acc[2][8][4];
    #pragma unroll
    for (int m = 0; m < 2; m++)
        #pragma unroll
        for (int n = 0; n < 8; n++)
            #pragma unroll
            for (int k = 0; k < 4; k++) acc[m][n][k] = 0.f;

    const float* cat = side ? cat_r : cat_l;
    const float* fin = cat + (size_t)b*CHW4 + (size_t)(g*64)*HW;
    const float* a_bn = g_aff[side*2] + g*64;
    const float* b_bn = g_aff[side*2+1] + g*64;
    const unsigned* wImg = g_w1h + g*4*4608;

    #pragma unroll 1
    for (int chunk = 0; chunk < 4; chunk++) {
        {
            const float4* src = (const float4*)(wImg + chunk*4608);
            float4* d4 = (float4*)sW;
            for (int e = tid; e < 1152; e += 256) d4[e] = src[e];
        }
        for (int it = tid; it < 1024; it += 256) {
            int p = it & 7, pl = (it >> 3) & 3, j = it >> 5;
            int s = (p < 4) ? 2*p : 2*p - 7;
            int yy = y0 + pl - 1;
            int icA = chunk*16 + 2*p;
            unsigned o0, o1, o2, o3;
            if ((unsigned)yy < 256u) {
                const float* pa = fin + (size_t)icA*HW + yy*256 + x0 + 4*j;
                float4 a = *(const float4*)pa;
                float4 bq = *(const float4*)(pa + HW);
                float ka = a_bn[icA], ba = b_bn[icA];
                float kb = a_bn[icA+1], bb = b_bn[icA+1];
                a.x = fmaf(ka,a.x,ba); a.y = fmaf(ka,a.y,ba);
                a.z = fmaf(ka,a.z,ba); a.w = fmaf(ka,a.w,ba);
                bq.x = fmaf(kb,bq.x,bb); bq.y = fmaf(kb,bq.y,bb);
                bq.z = fmaf(kb,bq.z,bb); bq.w = fmaf(kb,bq.w,bb);
                o0 = h2bits(a.x, bq.x); o1 = h2bits(a.y, bq.y);
                o2 = h2bits(a.z, bq.z); o3 = h2bits(a.w, bq.w);
            } else { o0 = o1 = o2 = o3 = 0u; }
            int base = pl*1064 + (4*j + 1)*8 + s;
            sIn[base] = o0; sIn[base+8] = o1; sIn[base+16] = o2; sIn[base+24] = o3;
        }
        if (tid < 64) {
            int p = tid >> 3, pl = (tid >> 1) & 3, right = tid & 1;
            int s = (p < 4) ? 2*p : 2*p - 7;
            int yy = y0 + pl - 1;
            int xx = right ? x0 + 128 : x0 - 1;
            int col = right ? 129 : 0;
            int icA = chunk*16 + 2*p;
            unsigned o = 0u;
            if ((unsigned)yy < 256u && (unsigned)xx < 256u) {
                size_t off = (size_t)icA*HW + yy*256 + xx;
                float lo = fin[off], hi = fin[off + HW];
                lo = fmaf(a_bn[icA], lo, b_bn[icA]);
                hi = fmaf(a_bn[icA+1], hi, b_bn[icA+1]);
                o = h2bits(lo, hi);
            }
            sIn[pl*1064 + col*8 + s] = o;
        }
        __syncthreads();
        mma_taps(sIn, sW, wset, wrow, wx, r4, c4, acc);
        __syncthreads();
    }

    // epilogue: bias + leaky + channel-pair shfl -> slot-interleaved store
    const float* b1g = b1 + g*64;
    size_t pxrow = ((size_t)(y0 + wrow)*256 + x0 + wx);
    #pragma unroll
    for (int mf = 0; mf < 2; mf++) {
        int oc = wset*32 + mf*16 + r4;
        float bv0 = b1g[oc], bv1 = b1g[oc + 8];
        int chunkc = wset*2 + mf;
        unsigned* cb = g_y2 + 8 + (size_t)((z*4 + g)*4 + chunkc)*524288 + pxrow*8 + r4;
        #pragma unroll
        for (int nf = 0; nf < 8; nf++) {
            float v0 = acc[mf][nf][0] + bv0; v0 = (v0 > 0.f) ? v0 : 0.1f*v0;
            float v1 = acc[mf][nf][1] + bv0; v1 = (v1 > 0.f) ? v1 : 0.1f*v1;
            float v2 = acc[mf][nf][2] + bv1; v2 = (v2 > 0.f) ? v2 : 0.1f*v2;
            float v3 = acc[mf][nf][3] + bv1; v3 = (v3 > 0.f) ? v3 : 0.1f*v3;
            float pv0 = __shfl_xor_sync(~0u, v0, 4);
            float pv1 = __shfl_xor_sync(~0u, v1, 4);
            float pv2 = __shfl_xor_sync(~0u, v2, 4);
            float pv3 = __shfl_xor_sync(~0u, v3, 4);
            unsigned* wp = cb + (nf*8 + 2*c4)*8;
            if ((r4 & 1) == 0) { wp[0] = h2bits(v0, pv0); wp[8] = h2bits(v1, pv1); }
            else               { wp[0] = h2bits(pv2, v2); wp[8] = h2bits(pv3, v3); }
        }
    }
}

// ------------------ conv2 + residual + grouped 1x1 projection ------------------
__global__ __launch_bounds__(256, 2) void conv2proj_kernel(
    const float* __restrict__ cat_l, const float* __restrict__ cat_r,
    const float* __restrict__ b2,
    const float* __restrict__ bq_w, const float* __restrict__ bs_w,
    const float* __restrict__ bq_b, const float* __restrict__ bs_b)
{
    __shared__ __align__(16) unsigned sm[9728];   // conv: sIn 4256 + sW 4608; epi: resbh 9216 + pwh 512
    unsigned* sIn = sm;
    unsigned* sW  = sm + 4256;
    int tile = blockIdx.x, g = blockIdx.y, z = blockIdx.z;
    int side = z >> 1, b = z & 1;
    int y0 = (tile >> 1) * 2, x0 = (tile & 1) * 128;
    int tid = threadIdx.x, lane = tid & 31, warp = tid >> 5;
    int wset = warp >> 2, w4 = warp & 3, wrow = w4 >> 1, wx = (w4 & 1) * 64;
    int r4 = lane >> 2, c4 = lane & 3;

    float acc[2][8][4];
    #pragma unroll
    for (int m = 0; m < 2; m++)
        #pragma unroll
        for (int n = 0; n < 8; n++)
            #pragma unroll
            for (int k = 0; k < 4; k++) acc[m][n][k] = 0.f;

    const unsigned* wImg = g_w2h + g*4*4608;
    int clo = (x0 == 0) ? 1 : 0;
    int chi = (x0 == 0) ? 130 : 129;

    #pragma unroll 1
    for (int chunk = 0; chunk < 4; chunk++) {
        {
            const float4* src = (const float4*)(wImg + chunk*4608);
            float4* d4 = (float4*)sW;
            for (int e = tid; e < 1152; e += 256) d4[e] = src[e];
        }
        // contiguous halo-inclusive copy from slot-interleaved g_y2
        {
            const unsigned* src = g_y2 + 8 + (size_t)((z*4 + g)*4 + chunk)*524288;
            int pl = tid >> 6, lt = tid & 63;
            int yy = y0 + pl - 1;
            bool rowok = (unsigned)yy < 256u;
            const float4* s4 = (const float4*)(src + ((size_t)yy*256 + x0 - 1)*8);
            float4* d4 = (float4*)(sIn + pl*1064);
            for (int f = lt; f < 260; f += 64) {
                int col = f >> 1;
                float4 v = make_float4(0.f, 0.f, 0.f, 0.f);
                if (rowok && col >= clo && col < chi) v = s4[f];
                d4[f] = v;
            }
        }
        __syncthreads();
        mma_taps(sIn, sW, wset, wrow, wx, r4, c4, acc);
        __syncthreads();
    }

    // ---- epilogue: resb = conv2 + b2 + bn(cat) (fp16) -> 1x1 projection mma
    __half* resbh = (__half*)sm;              // [256 px][72 halves]
    unsigned* pwh = sm + 9216;                // [16 oc][32 slot words]
    const float* cat = side ? cat_r : cat_l;
    const float* a_bn = g_aff[side*2] + g*64;
    const float* b_bn = g_aff[side*2+1] + g*64;
    const float* b2g = b2 + g*64;
    const float* pbg = (side ? bs_b : bq_b) + g*16;
    __half* qout = (side ? g_Kh : g_Qh) + (size_t)b*CHW1 + (size_t)(g*16)*HW;

    {
        const float* pwsrc = (side ? bs_w : bq_w) + (size_t)(g*16)*64;
        for (int e = tid; e < 512; e += 256) {
            int oc = e >> 5, w5 = e & 31;
            int kc = w5 >> 3, s = w5 & 7;
            int p = (s >> 1) + 4*(s & 1);
            int ic0 = kc*16 + 2*p;
            pwh[e] = h2bits(pwsrc[oc*64 + ic0], pwsrc[oc*64 + ic0 + 1]);
        }
    }
    {
        const float* catb = cat + (size_t)b*CHW4 + (size_t)(g*64)*HW
                          + (size_t)(y0 + wrow)*256 + x0;
        #pragma unroll
        for (int mf = 0; mf < 2; mf++) {
            int ch = wset*32 + mf*16 + r4;
            float bv0 = b2g[ch], bv1 = b2g[ch + 8];
            float a0c = a_bn[ch], b0c = b_bn[ch];
            float a1c = a_bn[ch+8], b1c = b_bn[ch+8];
            #pragma unroll
            for (int nf = 0; nf < 8; nf++) {
                int px = wx + nf*8 + 2*c4;
                int pxl = wrow*128 + px;
                float2 cv0 = *(const float2*)&catb[(size_t)ch*HW + px];
                float2 cv1 = *(const float2*)&catb[(size_t)(ch+8)*HW + px];
                resbh[pxl*72 + ch]       = __float2half_rn(acc[mf][nf][0] + bv0 + fmaf(a0c, cv0.x, b0c));
                resbh[(pxl+1)*72 + ch]   = __float2half_rn(acc[mf][nf][1] + bv0 + fmaf(a0c, cv0.y, b0c));
                resbh[pxl*72 + ch+8]     = __float2half_rn(acc[mf][nf][2] + bv1 + fmaf(a1c, cv1.x, b1c));
                resbh[(pxl+1)*72 + ch+8] = __float2half_rn(acc[mf][nf][3] + bv1 + fmaf(a1c, cv1.y, b1c));
            }
        }
    }
    __syncthreads();
    #pragma unroll
    for (int sb = 0; sb < 2; sb++) {
        int pm = warp*32 + sb*16;
        float PA[2][4];
        #pragma unroll
        for (int nf = 0; nf < 2; nf++) {
            float p0 = pbg[8*nf + 2*c4], p1 = pbg[8*nf + 2*c4 + 1];
            PA[nf][0] = p0; PA[nf][1] = p1; PA[nf][2] = p0; PA[nf][3] = p1;
        }
        #pragma unroll
        for (int kc = 0; kc < 4; kc++) {
            unsigned a0 = *(const unsigned*)&resbh[(pm + r4)*72 + kc*16 + 2*c4];
            unsigned a2 = *(const unsigned*)&resbh[(pm + r4)*72 + kc*16 + 2*c4 + 8];
            unsigned a1 = *(const unsigned*)&resbh[(pm + r4 + 8)*72 + kc*16 + 2*c4];
            unsigned a3 = *(const unsigned*)&resbh[(pm + r4 + 8)*72 + kc*16 + 2*c4 + 8];
            #pragma unroll
            for (int nf = 0; nf < 2; nf++) {
                uint2 bb = *(const uint2*)&pwh[(nf*8 + r4)*32 + kc*8 + 2*c4];
                MMA_F16S(PA[nf], a0, a1, a2, a3, bb.x, bb.y);
            }
        }
        #pragma unroll
        for (int nf = 0; nf < 2; nf++)
            #pragma unroll
            for (int e = 0; e < 2; e++) {
                int oc = 8*nf + 2*c4 + e;
                int pxa = pm + r4, pxb = pxa + 8;
                qout[(size_t)oc*HW + (size_t)(y0 + (pxa >> 7))*256 + x0 + (pxa & 127)] = __float2half_rn(PA[nf][e]);
                qout[(size_t)oc*HW + (size_t)(y0 + (pxb >> 7))*256 + x0 + (pxb & 127)] = __float2half_rn(PA[nf][2+e]);
            }
    }
}

// ------------------ merged transpose-gather (one launch, fp16 in/out) ------------------
__global__ __launch_bounds__(256) void gather_kernel(
    const float* __restrict__ xl, const float* __restrict__ xr,
    const int* __restrict__ dl, const int* __restrict__ dr)
{
    __shared__ float s[64][113];
    int x0 = blockIdx.x * 64;
    int y  = blockIdx.y;
    int zb = blockIdx.z;
    int b = zb >> 2, which = zb & 3;
    const float* fsrc = nullptr; const __half* hsrc = nullptr;
    __half* dst; const int* dvals; int mode;
    switch (which) {
        case 0: hsrc = g_Qh; dst = g_GQh;  dvals = dr; mode = 0; break;
        case 1: hsrc = g_Kh; dst = g_GKh;  dvals = dl; mode = 1; break;
        case 2: fsrc = xr;   dst = g_GXRh; dvals = dl; mode = 1; break;
        default: fsrc = xl;  dst = g_GXLh; dvals = dr; mode = 0; break;
    }
    int lo = (mode == 0) ? x0 : max(x0 - 48, 0);
    int t = threadIdx.x;
    size_t rowbase = (size_t)b*CHW1 + y*256;
    for (int e = t; e < 64*112; e += 256) {
        int c = e / 112, j = e - c*112;
        int col = min(lo + j, 255);
        size_t off = rowbase + (size_t)c*HW + col;
        s[c][j] = hsrc ? __half2float(hsrc[off]) : fsrc[off];
    }
    __syncthreads();
    __half* db = dst + (size_t)b*CHW1 + y*16384 + x0*64;
    const int* dp = dvals + b*HW + y*256;
    for (int e = t; e < 4096; e += 256) {
        int xi = e >> 6, c = e & 63;
        int x = x0 + xi;
        int d = dp[x];
        int sc = (mode == 0) ? min(x + d, 255) : max(x - d, 0);
        db[xi*64 + c] = __float2half_rn(s[c][sc - lo]);
    }
}

// ------------------ per-window attention (fp16 mma) + output assembly ------------------
__global__ __launch_bounds__(128) void attn_kernel(
    const float* __restrict__ xl, const float* __restrict__ xr,
    const int* __restrict__ dl, const int* __restrict__ dr,
    float* __restrict__ out)
{
    __shared__ float sRaw[64][68];
    __shared__ __align__(16) unsigned sA[2048];
    __shared__ __align__(16) unsigned sB[2048];
    __shared__ float mu[8];
    int win = blockIdx.x, side = blockIdx.y, b = blockIdx.z;
    int hi = win >> 5, wi = win & 31;
    int t = threadIdx.x, lane = t & 31, warp = t >> 5;
    int q4 = lane & 3, r4 = lane >> 2;

    const __half *Ab, *Bb, *Xb;
    if (side == 0) { Ab = g_Qh; Bb = g_GKh; Xb = g_GXRh; }
    else           { Ab = g_Kh; Bb = g_GQh; Xb = g_GXLh; }
    size_t base = (size_t)b*CHW1 + (size_t)(hi*8)*256 + wi*8;

    for (int e = t; e < 4096; e += 128) {
        int j = e & 63, c = e >> 6;
        sRaw[j][c] = __half2float(Ab[base + (size_t)c*HW + ((j >> 3)*256 + (j & 7))]);
    }
    __syncthreads();
    for (int e = t; e < 2048; e += 128) {
        int i = e >> 5, w5 = e & 31;
        int kc = w5 >> 3, s = w5 & 7;
        int p = (s >> 1) + 4*(s & 1);
        int c0 = kc*16 + 2*p;
        sA[e] = h2bits(sRaw[i][c0], sRaw[i][c0+1]);
    }
    __syncthreads();
    for (int e = t; e < 4096; e += 128) {
        int j = e & 63, c = e >> 6;
        sRaw[j][c] = __half2float(Bb[base + (size_t)c*HW + ((j >> 3)*256 + (j & 7))]);
    }
    __syncthreads();
    {
        int p = t >> 4, sub = t & 15;
        float s = 0.f;
        #pragma unroll 4
        for (int m = 0; m < 32; m++) {
            int el = sub*32 + m;
            s += sRaw[8*p + (el >> 6)][el & 63];
        }
        s += __shfl_xor_sync(~0u, s, 8);
        s += __shfl_xor_sync(~0u, s, 4);
        s += __shfl_xor_sync(~0u, s, 2);
        s += __shfl_xor_sync(~0u, s, 1);
        if (sub == 0) mu[p] = s * (1.f/512.f);
    }
    __syncthreads();
    for (int e = t; e < 2048; e += 128) {
        int j = e >> 5, w5 = e & 31;
        int kc = w5 >> 3, s = w5 & 7;
        int p = (s >> 1) + 4*(s & 1);
        int c0 = kc*16 + 2*p;
        float m = mu[j >> 3];
        sB[e] = h2bits(sRaw[j][c0] - m, sRaw[j][c0+1] - m);
    }
    __syncthreads();

    int m0 = warp * 16;
    float S[8][4];
    #pragma unroll
    for (int nf = 0; nf < 8; nf++)
        #pragma unroll
        for (int k = 0; k < 4; k++) S[nf][k] = 0.f;
    #pragma unroll
    for (int kc = 0; kc < 4; kc++) {
        uint2 alo = *(const uint2*)&sA[(m0 + r4)*32 + kc*8 + q4*2];
        uint2 ahi = *(const uint2*)&sA[(m0 + r4 + 8)*32 + kc*8 + q4*2];
        #pragma unroll
        for (int nf = 0; nf < 8; nf++) {
            uint2 bb = *(const uint2*)&sB[(nf*8 + r4)*32 + kc*8 + q4*2];
            MMA_F16S(S[nf], alo.x, ahi.x, alo.y, ahi.y, bb.x, bb.y);
        }
    }
    float mlo = -1e30f, mhi = -1e30f;
    #pragma unroll
    for (int nf = 0; nf < 8; nf++) {
        mlo = fmaxf(mlo, fmaxf(S[nf][0], S[nf][1]));
        mhi = fmaxf(mhi, fmaxf(S[nf][2], S[nf][3]));
    }
    mlo = fmaxf(mlo, __shfl_xor_sync(~0u, mlo, 1));
    mlo = fmaxf(mlo, __shfl_xor_sync(~0u, mlo, 2));
    mhi = fmaxf(mhi, __shfl_xor_sync(~0u, mhi, 1));
    mhi = fmaxf(mhi, __shfl_xor_sync(~0u, mhi, 2));
    float slo = 0.f, shi = 0.f;
    #pragma unroll
    for (int nf = 0; nf < 8; nf++) {
        S[nf][0] = __expf(S[nf][0] - mlo); S[nf][1] = __expf(S[nf][1] - mlo);
        S[nf][2] = __expf(S[nf][2] - mhi); S[nf][3] = __expf(S[nf][3] - mhi);
        slo += S[nf][0] + S[nf][1];
        shi += S[nf][2] + S[nf][3];
    }
    slo += __shfl_xor_sync(~0u, slo, 1);
    slo += __shfl_xor_sync(~0u, slo, 2);
    shi += __shfl_xor_sync(~0u, shi, 1);
    shi += __shfl_xor_sync(~0u, shi, 2);
    float invlo = 1.f / slo, invhi = 1.f / shi;
    unsigned pa[4][4];
    #pragma unroll
    for (int kc = 0; kc < 4; kc++) {
        pa[kc][0] = h2bits(S[2*kc][0]*invlo,   S[2*kc][1]*invlo);
        pa[kc][1] = h2bits(S[2*kc][2]*invhi,   S[2*kc][3]*invhi);
        pa[kc][2] = h2bits(S[2*kc+1][0]*invlo, S[2*kc+1][1]*invlo);
        pa[kc][3] = h2bits(S[2*kc+1][2]*invhi, S[2*kc+1][3]*invhi);
    }
    __syncthreads();

    for (int e = t; e < 4096; e += 128) {
        int j = e & 63, c = e >> 6;
        sRaw[j][c] = __half2float(Xb[base + (size_t)c*HW + ((j >> 3)*256 + (j & 7))]);
    }
    __syncthreads();
    for (int e = t; e < 2048; e += 128) {
        int c = e >> 5, w5 = e & 31;
        int kc = w5 >> 3, s = w5 & 7;
        int p = (s >> 1) + 4*(s & 1);
        int j0 = kc*16 + 2*p;
        sB[e] = h2bits(sRaw[j0][c], sRaw[j0+1][c]);
    }
    __syncthreads();
    float O[8][4];
    #pragma unroll
    for (int nf = 0; nf < 8; nf++)
        #pragma unroll
        for (int k = 0; k < 4; k++) O[nf][k] = 0.f;
    #pragma unroll
    for (int kc = 0; kc < 4; kc++) {
        #pragma unroll
        for (int nf = 0; nf < 8; nf++) {
            uint2 bb = *(const uint2*)&sB[(nf*8 + r4)*32 + kc*8 + q4*2];
            MMA_F16S(O[nf], pa[kc][0], pa[kc][1], pa[kc][2], pa[kc][3], bb.x, bb.y);
        }
    }
    int ilo = m0 + r4, ihi = ilo + 8;
    int Ylo = hi*8 + (ilo >> 3), Xlo = wi*8 + (ilo & 7);
    int Yhi = hi*8 + (ihi >> 3), Xhi = wi*8 + (ihi & 7);
    const float* xbase = side ? xr : xl;
    float mv_lo, mv_hi;
    if (side == 0) {
        mv_lo = (Xlo - dl[b*HW + Ylo*256 + Xlo] >= 0) ? 1.f : 0.f;
        mv_hi = (Xhi - dl[b*HW + Yhi*256 + Xhi] >= 0) ? 1.f : 0.f;
    } else {
        mv_lo = (Xlo + dr[b*HW + Ylo*256 + Xlo] <= 255) ? 1.f : 0.f;
        mv_hi = (Xhi + dr[b*HW + Yhi*256 + Xhi] <= 255) ? 1.f : 0.f;
    }
    size_t offlo = (size_t)b*CHW1 + Ylo*256 + Xlo;
    size_t offhi = (size_t)b*CHW1 + Yhi*256 + Xhi;
    float* ob = out + (size_t)side*HALF_OUT;
    #pragma unroll
    for (int nf = 0; nf < 8; nf++)
        #pragma unroll
        for (int e = 0; e < 2; e++) {
            size_t go = (size_t)(8*nf + 2*q4 + e) * HW;
            ob[offlo + go] = xbase[offlo + go] + O[nf][e]   * mv_lo;
            ob[offhi + go] = xbase[offhi + go] + O[nf][2+e] * mv_hi;
        }
}

// ------------------ launch ------------------
extern "C" void kernel_launch(void* const* d_in, const int* in_sizes, int n_in,
                              void* d_out, int out_size)
{
    (void)in_sizes; (void)n_in; (void)out_size;
    const float* x_left  = (const float*)d_in[0];
    const float* x_right = (const float*)d_in[1];
    const float* cat_l   = (const float*)d_in[2];
    const float* cat_r   = (const float*)d_in[3];
    const int*   d_left  = (const int*)d_in[4];
    const int*   d_right = (const int*)d_in[5];
    const float* gamma   = (const float*)d_in[6];
    const float* beta    = (const float*)d_in[7];
    const float* rb_w1   = (const float*)d_in[8];
    const float* rb_b1   = (const float*)d_in[9];
    const float* rb_w2   = (const float*)d_in[10];
    const float* rb_b2   = (const float*)d_in[11];
    const float* bq_w    = (const float*)d_in[12];
    const float* bq_b    = (const float*)d_in[13];
    const float* bs_w    = (const float*)d_in[14];
    const float* bs_b    = (const float*)d_in[15];
    float* out = (float*)d_out;

    bn_stats_kernel<<<256, 256>>>(cat_l, gamma, beta, 0);
    bn_stats_kernel<<<256, 256>>>(cat_r, gamma, beta, 1);
    prep_w_kernel<<<dim3(16, 2), 256>>>(rb_w1, rb_w2);

    dim3 cgrid(256, 4, 4);   // 128 y-tiles x 2 x-halves, 4 groups, z = side*2+b
    conv1_kernel    <<<cgrid, 256>>>(cat_l, cat_r, rb_b1);
    conv2proj_kernel<<<cgrid, 256>>>(cat_l, cat_r, rb_b2, bq_w, bs_w, bq_b, bs_b);

    gather_kernel<<<dim3(4, 256, 8), 256>>>(x_left, x_right, d_left, d_right);

    attn_kernel<<<dim3(1024, 2, 2), 128>>>(x_left, x_right, d_left, d_right, out);
}